// round 17
// baseline (speedup 1.0000x reference)
#include <cuda_runtime.h>
#include <cstdint>
#include <math.h>

#define N_ROWS   524288
#define W        101
#define LAMBDA_1 0.2
#define LAMBDA_2 0.05
#define EPS_F    1e-3f

#define TILE     16                        // rows per smem buffer
#define THREADS  128                       // 8 threads per row, 4 warps
#define SROW     104                       // fp32 words per smem row (3 pad)
#define NTILES   (N_ROWS / TILE)           // 32768
#define BPSM     14
#define GRID     (148 * BPSM)              // 2072 persistent blocks

// exact constants for the scalar finalize (double)
#define D_LN2    0.6931471805599453
#define D_C0     6.907755278982137e-3      // -eps*ln(eps)
#define D_EPSLG2 (-9.965784284662087e-3)   // eps*log2(eps)

__device__ double   g_sum[3];              // [0]=sum d^2, [1]=raw sum q*lg2 q, [2]=sum K
__device__ unsigned g_ticket;

__device__ __forceinline__ unsigned warp_redux_add_u32(unsigned v) {
    unsigned r;
    asm volatile("redux.sync.add.u32 %0, %1, 0xffffffff;" : "=r"(r) : "r"(v));
    return r;
}
__device__ __forceinline__ unsigned int smem_u32(const void* p) {
    unsigned int a;
    asm("{ .reg .u64 t; cvta.to.shared.u64 t, %1; cvt.u32.u64 %0, t; }" : "=r"(a) : "l"(p));
    return a;
}
// cp.async with separate literal offsets for dst (smem, 416B row stride)
// and src (global, 404B row stride) — zero per-copy address arithmetic.
#define CP4_OFF2(dst, doff, src, soff) \
    asm volatile("cp.async.ca.shared.global [%0+" #doff "], [%1+" #soff "], 4;" \
                 :: "r"(dst), "l"(src))
__device__ __forceinline__ void cp_commit() { asm volatile("cp.async.commit_group;"); }
__device__ __forceinline__ void cp_wait1()  { asm volatile("cp.async.wait_group 1;"); }

// warp stages its 4 rows from one smem base + one global base, all-immediate offsets
__device__ __forceinline__ void stage4(unsigned int s, const float* g, bool tail) {
    CP4_OFF2(s,    0, g,    0); CP4_OFF2(s,  128, g,  128); CP4_OFF2(s,  256, g,  256);
    CP4_OFF2(s,  416, g,  404); CP4_OFF2(s,  544, g,  532); CP4_OFF2(s,  672, g,  660);
    CP4_OFF2(s,  832, g,  808); CP4_OFF2(s,  960, g,  936); CP4_OFF2(s, 1088, g, 1064);
    CP4_OFF2(s, 1248, g, 1212); CP4_OFF2(s, 1376, g, 1340); CP4_OFF2(s, 1504, g, 1468);
    if (tail) {                         // lanes 0..4: bins 96..100 of each row
        CP4_OFF2(s,  384, g,  384);
        CP4_OFF2(s,  800, g,  788);
        CP4_OFF2(s, 1216, g, 1192);
        CP4_OFF2(s, 1632, g, 1596);
    }
}

__global__ void __launch_bounds__(THREADS, BPSM)
mrl_kernel(const float* __restrict__ inp, const int* __restrict__ tgt,
           float* __restrict__ out) {
    __shared__ float  sm[2][TILE * SROW];  // 2 x 6,656 B
    __shared__ double sb[(THREADS / 32) * 3];

    const int tid  = threadIdx.x;
    const int lane = tid & 31;
    const int warp = tid >> 5;
    const int sub  = tid & 7;              // slot within 8-thread row group
    const int rloc = tid >> 3;             // row within tile = 4*warp + (lane>>3)
    const int c4   = 4 * sub;              // float4 chunk offset within row
    const bool tail = (lane < 5);

    // per-warp staging bases for both buffers (rows 4w..4w+3, +lane within row)
    const unsigned int stA = smem_u32(&sm[0][0]) + (unsigned)(warp * 4 * SROW + lane) * 4u;
    const unsigned int stB = smem_u32(&sm[1][0]) + (unsigned)(warp * 4 * SROW + lane) * 4u;

    // pad columns 101..103 of every row, both buffers (never overwritten).
    if (tid < TILE) {
        #pragma unroll
        for (int b = 0; b < 2; b++) {
            sm[b][tid * SROW + 101] = -1000.f;
            sm[b][tid * SROW + 102] = -1000.f;
            sm[b][tid * SROW + 103] = -1000.f;
        }
    }
    __syncthreads();                       // one-time: pads visible to all warps

    // running pointers (strength-reduced; constant strides)
    const int tile0 = blockIdx.x;
    const float* gst = inp + (size_t)tile0 * (TILE * W) + warp * (4 * W) + lane;
    const int*   tp  = tgt + tile0 * TILE + rloc;

    // prologue: stage first tile into buf0; prefetch its target
    stage4(stA, gst, tail);
    int tcur = *tp;
    cp_commit();
    gst += (size_t)GRID * (TILE * W);
    tp  += GRID * TILE;

    float    accM = 0.f, accQ = 0.f;
    unsigned accK = 0u;
    int cur = 0;

    for (int tile = tile0; tile < NTILES; tile += GRID) {
        // stage next tile (this warp's rows) into the other buffer
        int tnext = 0;
        if (tile + GRID < NTILES) {
            stage4(cur ? stA : stB, gst, tail);
            tnext = *tp;
        }
        cp_commit();
        cp_wait1();                        // current tile's copies complete
        __syncwarp();                      // warp-local data: warp barrier suffices

        // ---- pass 1: vector loads, exp into registers, (s, wn) ----
        const float* xr = &sm[cur][rloc * SROW];
        float4 A = *reinterpret_cast<const float4*>(xr + c4);
        float4 B = *reinterpret_cast<const float4*>(xr + 32 + c4);
        float4 C = *reinterpret_cast<const float4*>(xr + 64 + c4);
        float  vD = xr[96 + sub];          // subs 5..7 hit pads (-1000 -> e=0)

        float e[13];
        e[0]  = __expf(A.x); e[1]  = __expf(A.y); e[2]  = __expf(A.z); e[3]  = __expf(A.w);
        e[4]  = __expf(B.x); e[5]  = __expf(B.y); e[6]  = __expf(B.z); e[7]  = __expf(B.w);
        e[8]  = __expf(C.x); e[9]  = __expf(C.y); e[10] = __expf(C.z); e[11] = __expf(C.w);
        e[12] = __expf(vD);

        float s  = e[0] + e[1] + e[2] + e[3] + e[4] + e[5] + e[6] + e[7]
                 + e[8] + e[9] + e[10] + e[11];
        float m1 = 0.f;
        m1 = fmaf( 1.f, e[1], m1);  m1 = fmaf( 2.f, e[2],  m1); m1 = fmaf( 3.f, e[3],  m1);
        m1 = fmaf(32.f, e[4], m1);  m1 = fmaf(33.f, e[5],  m1); m1 = fmaf(34.f, e[6],  m1);
        m1 = fmaf(35.f, e[7], m1);  m1 = fmaf(64.f, e[8],  m1); m1 = fmaf(65.f, e[9],  m1);
        m1 = fmaf(66.f, e[10], m1); m1 = fmaf(67.f, e[11], m1);
        float wn = fmaf((float)c4, s, m1);
        s  += e[12];
        wn  = fmaf((float)(96 + sub), e[12], wn);

        // reduce (s, wn) over the 8-thread row group (within warp)
        #pragma unroll
        for (int o = 1; o < 8; o <<= 1) {
            s  += __shfl_xor_sync(0xffffffffu, s,  o);
            wn += __shfl_xor_sync(0xffffffffu, wn, o);
        }

        const int   t   = tcur;
        const float et  = __expf(sm[cur][rloc * SROW + t]);  // bit-identical to owner's e_t
        const float inv = __fdividef(1.f, s);

        if (sub == 0) {
            float d = fmaf(wn, inv, -(float)t);
            accM = fmaf(d, d, accM);
        }

        // ---- pass 2: register-resident residue + K (predicated) ----
        #pragma unroll
        for (int i = 0; i < 13; i++) {
            float q  = fmaf(e[i], inv, EPS_F);
            float lq = __log2f(q);
            if (e[i] < et) {               // == (p < pg); pads always below
                accQ = fmaf(q, lq, accQ);
            } else {
                accK++;
            }
        }
        __syncwarp();                      // warp done reading buf[cur] before re-stage

        gst += (size_t)GRID * (TILE * W);
        tp  += GRID * TILE;
        tcur = tnext;
        cur ^= 1;
    }

    // ---- block + grid reduction ----
    #pragma unroll
    for (int o = 16; o; o >>= 1) {
        accM += __shfl_xor_sync(0xffffffffu, accM, o);
        accQ += __shfl_xor_sync(0xffffffffu, accQ, o);
    }
    accK = warp_redux_add_u32(accK);

    if (lane == 0) {
        sb[warp * 3 + 0] = (double)accM;
        sb[warp * 3 + 1] = (double)accQ;
        sb[warp * 3 + 2] = (double)accK;
    }
    __syncthreads();

    if (tid == 0) {
        double tM = 0.0, tQ = 0.0, tK = 0.0;
        #pragma unroll
        for (int i = 0; i < THREADS / 32; i++) {
            tM += sb[i * 3 + 0];
            tQ += sb[i * 3 + 1];
            tK += sb[i * 3 + 2];
        }
        atomicAdd(&g_sum[0], tM);
        atomicAdd(&g_sum[1], tQ);
        atomicAdd(&g_sum[2], tK);
        __threadfence();
        unsigned old = atomicAdd(&g_ticket, 1u);
        if (old == (unsigned)(GRID - 1)) {
            volatile double* gs = g_sum;
            double M = gs[0];
            double Q = gs[1];
            double K = gs[2];
            // remove 3 pad bins per row (each contributed eps*lg2(eps) to Q)
            double Qadj = Q - 3.0 * (double)N_ROWS * D_EPSLG2;
            double residue_sum = -D_LN2 * Qadj + D_C0 * K;
            const double invN = 1.0 / (double)N_ROWS;
            out[0] = (float)(LAMBDA_1 * 0.5 * M * invN);
            out[1] = (float)(LAMBDA_2 * residue_sum * invN);
            out[2] = (float)(K * invN);
            gs[0] = 0.0; gs[1] = 0.0; gs[2] = 0.0;
            __threadfence();
            g_ticket = 0u;
        }
    }
}

extern "C" void kernel_launch(void* const* d_in, const int* in_sizes, int n_in,
                              void* d_out, int out_size) {
    const float* inp = (const float*)d_in[0];
    const int*   tgt = (const int*)d_in[1];
    float*       out = (float*)d_out;
    (void)in_sizes; (void)n_in; (void)out_size;

    mrl_kernel<<<GRID, THREADS>>>(inp, tgt, out);
}